// round 6
// baseline (speedup 1.0000x reference)
#include <cuda_runtime.h>

// mysoftmax: per-pixel softmax over C=19 + variance propagation through the
// squared softmax Jacobian.
//   p = softmax(mu)
//   sigma_out_i = p_i^2 * ( S + (1 - 2 p_i) * sigma_i ),  S = sum_j p_j^2 sigma_j
//
// d_out layout: [p (B*N*C floats), sigma_out (B*N*C floats)]
//
// R6: R5 structure + STREAMING STORES (__stcs, evict-first) on both outputs.
// Across graph replays the DRAM stream is ~pure output write-back at a pinned
// 2.7-2.8 TB/s regardless of kernel structure; evict-first keeps the 40MB of
// dirty output lines from churning L2 (protecting input residency) and lets
// them drain in-order to DRAM.

static constexpr int C = 19;
static constexpr int PIX_PER_BLK = 128;
static constexpr int TILE  = PIX_PER_BLK * C;   // 2432 floats
static constexpr int TILE4 = TILE / 4;          // 608 float4
static constexpr int NITER = (TILE4 + PIX_PER_BLK - 1) / PIX_PER_BLK;  // 5

__global__ __launch_bounds__(PIX_PER_BLK)
void mysoftmax_kernel(const float* __restrict__ mu,
                      const float* __restrict__ sg,
                      float* __restrict__ out,
                      long long total_elems)   // B*N*C
{
    __shared__ __align__(16) float  smu[TILE];
    __shared__ __align__(16) float  ssg[TILE];
    __shared__ __align__(8)  float2 invS[PIX_PER_BLK];

    const int t = threadIdx.x;
    const long long base = (long long)blockIdx.x * TILE;

    // ---- coalesced vectorized load: gmem -> (regs, smem) ----
    const float4* __restrict__ mu4 = reinterpret_cast<const float4*>(mu + base);
    const float4* __restrict__ sg4 = reinterpret_cast<const float4*>(sg + base);
    float4* smu4 = reinterpret_cast<float4*>(smu);
    float4* ssg4 = reinterpret_cast<float4*>(ssg);

    float4 rmu[NITER];                    // coalesced mu copy stays in registers
    #pragma unroll
    for (int i = 0; i < NITER; i++) {
        int idx = t + i * PIX_PER_BLK;
        if (idx < TILE4) {
            rmu[i] = mu4[idx];
            smu4[idx] = rmu[i];
            ssg4[idx] = sg4[idx];
        }
    }
    __syncthreads();

    // ---- per-pixel reduction (thread t <-> pixel t) ----
    // smem row stride 19 (odd) -> bank-conflict-free across the warp.
    {
        const int row = t * C;
        float s0 = 0.f, s1 = 0.f;       // sum of e_j
        float q0 = 0.f, q1 = 0.f;       // sum of e_j^2 * sigma_j
        #pragma unroll
        for (int j = 0; j < C; j++) {
            const float e = __expf(smu[row + j]);
            const float g = ssg[row + j];
            if (j & 1) { s1 += e; q1 = fmaf(e * e, g, q1); }
            else       { s0 += e; q0 = fmaf(e * e, g, q0); }
        }
        const float inv = __frcp_rn(s0 + s1);
        invS[t] = make_float2(inv, (q0 + q1) * inv * inv);
    }
    __syncthreads();

    // ---- output pass: coalesced layout, streaming stores straight to gmem ----
    float4* __restrict__ outp = reinterpret_cast<float4*>(out + base);
    float4* __restrict__ outs = reinterpret_cast<float4*>(out + total_elems + base);

    #pragma unroll
    for (int i = 0; i < NITER; i++) {
        int idx = t + i * PIX_PER_BLK;
        if (idx < TILE4) {
            const float4 m4 = rmu[i];
            const float4 g4 = ssg4[idx];          // vectorized sigma re-read
            const unsigned e0 = (unsigned)idx * 4u;

            float4 p4, s4;
            {
                const float2 a = invS[(e0 + 0u) / 19u];
                const float p = __expf(m4.x) * a.x;
                p4.x = p; s4.x = p * p * fmaf(1.0f - 2.0f * p, g4.x, a.y);
            }
            {
                const float2 a = invS[(e0 + 1u) / 19u];
                const float p = __expf(m4.y) * a.x;
                p4.y = p; s4.y = p * p * fmaf(1.0f - 2.0f * p, g4.y, a.y);
            }
            {
                const float2 a = invS[(e0 + 2u) / 19u];
                const float p = __expf(m4.z) * a.x;
                p4.z = p; s4.z = p * p * fmaf(1.0f - 2.0f * p, g4.z, a.y);
            }
            {
                const float2 a = invS[(e0 + 3u) / 19u];
                const float p = __expf(m4.w) * a.x;
                p4.w = p; s4.w = p * p * fmaf(1.0f - 2.0f * p, g4.w, a.y);
            }

            __stcs(&outp[idx], p4);   // streaming / evict-first
            __stcs(&outs[idx], s4);
        }
    }
}

extern "C" void kernel_launch(void* const* d_in, const int* in_sizes, int n_in,
                              void* d_out, int out_size)
{
    const float* mu = (const float*)d_in[0];
    const float* sg = (const float*)d_in[1];
    float* out = (float*)d_out;

    const long long total_elems = (long long)in_sizes[0];        // B*N*C = 4,980,736
    const int n_pix = (int)(total_elems / C);                    // 262,144
    const int n_blocks = n_pix / PIX_PER_BLK;                    // 2048

    mysoftmax_kernel<<<n_blocks, PIX_PER_BLK>>>(mu, sg, out, total_elems);
}